// round 11
// baseline (speedup 1.0000x reference)
#include <cuda_runtime.h>
#include <cuda_bf16.h>
#include <math_constants.h>

// BBOX_XFORM_CLIP = log(1000/16)
#define BBOX_XFORM_CLIP 4.135166556742356f

#define HALF_ROWS 4                  // rows per half-tile (one row per warp)
#define ROWS_PER_BLOCK (2 * HALF_ROWS)
#define THREADS 128                  // 4 warps

#define BOX_HALF_BYTES (HALF_ROWS * 81 * 16)   // 5184
#define SC_HALF_BYTES  (HALF_ROWS * 81 * 4)    // 1296

// img dims may arrive as int32 or float32; disambiguate by plausibility.
__device__ __forceinline__ float load_dim(const void* p) {
    int iv = *(const int*)p;
    if (iv > 0 && iv < (1 << 20)) return (float)iv;
    return __int_as_float(iv);
}

struct RowOut {
    float4 box;
    float sc0, sc1, sc2;
};

__device__ __forceinline__ RowOut process_row(
    const float* __restrict__ logits,
    const float* __restrict__ regr,
    const float* __restrict__ prop,
    int n, int lane, float wmax, float hmax)
{
    // front-batch all 5 independent loads (MLP=5) before any consumer
    const float4 b  = reinterpret_cast<const float4*>(prop)[n];
    const float4 rc = reinterpret_cast<const float4*>(regr)[n];

    const float* lrow = logits + (size_t)n * 81;
    float v0 = lrow[lane];
    float v1 = lrow[lane + 32];
    float v2 = (lane < 17) ? lrow[lane + 64] : -CUDART_INF_F;

    // ---------------- softmax over 81 logits ----------------
    float m = fmaxf(fmaxf(v0, v1), v2);
    #pragma unroll
    for (int o = 16; o; o >>= 1)
        m = fmaxf(m, __shfl_xor_sync(0xffffffffu, m, o));

    float e0 = __expf(v0 - m);
    float e1 = __expf(v1 - m);
    float e2 = (lane < 17) ? __expf(v2 - m) : 0.0f;

    float s = e0 + e1 + e2;
    #pragma unroll
    for (int o = 16; o; o >>= 1)
        s += __shfl_xor_sync(0xffffffffu, s, o);
    const float inv = __fdividef(1.0f, s);

    // ---------------- bbox decode (all lanes redundantly) ----------------
    const float w  = b.z - b.x + 1.0f;
    const float h  = b.w - b.y + 1.0f;
    const float cx = b.x + 0.5f * w;
    const float cy = b.y + 0.5f * h;

    const float dx = rc.x * 0.1f;
    const float dy = rc.y * 0.1f;
    const float dw = fminf(rc.z * 0.2f, BBOX_XFORM_CLIP);
    const float dh = fminf(rc.w * 0.2f, BBOX_XFORM_CLIP);

    const float pcx = dx * w + cx;
    const float pcy = dy * h + cy;
    const float pw  = __expf(dw) * w;
    const float ph  = __expf(dh) * h;

    float x1 = pcx - 0.5f * pw;
    float y1 = pcy - 0.5f * ph;
    float x2 = pcx + 0.5f * pw - 1.0f;
    float y2 = pcy + 0.5f * ph - 1.0f;

    // max(...,0) then clip(0,max) == clamp to [0,max]
    RowOut r;
    r.box = make_float4(fminf(fmaxf(x1, 0.0f), wmax),
                        fminf(fmaxf(y1, 0.0f), hmax),
                        fminf(fmaxf(x2, 0.0f), wmax),
                        fminf(fmaxf(y2, 0.0f), hmax));
    r.sc0 = e0 * inv;
    r.sc1 = e1 * inv;
    r.sc2 = e2 * inv;
    return r;
}

__device__ __forceinline__ void stage_row(float* s_box, float* s_sc,
                                          int lr, int lane, const RowOut& r)
{
    float4* sb = reinterpret_cast<float4*>(s_box) + lr * 81;
    sb[lane]      = r.box;
    sb[lane + 32] = r.box;
    if (lane < 17) sb[lane + 64] = r.box;

    float* ss = s_sc + lr * 81;
    ss[lane]      = r.sc0;
    ss[lane + 32] = r.sc1;
    if (lane < 17) ss[lane + 64] = r.sc2;
}

__device__ __forceinline__ void commit_half(const float* s_box, const float* s_sc,
                                            float* boxes_out, float* scores_out,
                                            long long half_idx)
{
    asm volatile("fence.proxy.async.shared::cta;" ::: "memory");
    unsigned sb_a = (unsigned)__cvta_generic_to_shared(s_box);
    unsigned ss_a = (unsigned)__cvta_generic_to_shared(s_sc);
    char* gb = (char*)boxes_out  + (size_t)half_idx * BOX_HALF_BYTES;
    char* gs = (char*)scores_out + (size_t)half_idx * SC_HALF_BYTES;
    asm volatile("cp.async.bulk.global.shared::cta.bulk_group [%0], [%1], %2;"
                 :: "l"(gb), "r"(sb_a), "n"(BOX_HALF_BYTES) : "memory");
    asm volatile("cp.async.bulk.global.shared::cta.bulk_group [%0], [%1], %2;"
                 :: "l"(gs), "r"(ss_a), "n"(SC_HALF_BYTES) : "memory");
    asm volatile("cp.async.bulk.commit_group;" ::: "memory");
}

__global__ void __launch_bounds__(THREADS)
postproc_kernel(const float* __restrict__ logits,       // [N,81]
                const float* __restrict__ regr,         // [N,4]
                const float* __restrict__ prop,         // [N,4]
                const void*  __restrict__ imw_p,
                const void*  __restrict__ imh_p,
                float* __restrict__ boxes_out,          // [N*81,4]
                float* __restrict__ scores_out,         // [N*81]
                int N)
{
    __shared__ alignas(16) float s_box[2][HALF_ROWS * 81 * 4];  // 2x5184 B
    __shared__ alignas(16) float s_sc [2][HALF_ROWS * 81];      // 2x1296 B

    const int warp = threadIdx.x >> 5;
    const int lane = threadIdx.x & 31;
    const int r0   = blockIdx.x * ROWS_PER_BLOCK;

    const float wmax = load_dim(imw_p) - 1.0f;
    const float hmax = load_dim(imh_p) - 1.0f;

    if (r0 + ROWS_PER_BLOCK <= N) {
        // ---------------- half A: all warps compute + stage ----------------
        {
            const int n = r0 + warp;
            RowOut r = process_row(logits, regr, prop, n, lane, wmax, hmax);
            stage_row(s_box[0], s_sc[0], warp, lane, r);
        }
        // producer/consumer barrier 1: warps 1-3 arrive (release) and move on;
        // warp 0 syncs (acquire) and commits half A
        if (warp == 0) {
            asm volatile("bar.sync 1, %0;" :: "n"(THREADS) : "memory");
            if (lane == 0)
                commit_half(s_box[0], s_sc[0], boxes_out, scores_out,
                            2LL * blockIdx.x);      // no wait: drains under half B
        } else {
            asm volatile("bar.arrive 1, %0;" :: "n"(THREADS) : "memory");
        }

        // ---------------- half B: overlaps half A's commit + drain ----------
        {
            const int n = r0 + HALF_ROWS + warp;
            RowOut r = process_row(logits, regr, prop, n, lane, wmax, hmax);
            stage_row(s_box[1], s_sc[1], warp, lane, r);
        }
        if (warp == 0) {
            asm volatile("bar.sync 2, %0;" :: "n"(THREADS) : "memory");
            if (lane == 0) {
                commit_half(s_box[1], s_sc[1], boxes_out, scores_out,
                            2LL * blockIdx.x + 1);
                // CTA must stay alive until the bulk engine has read both buffers
                asm volatile("cp.async.bulk.wait_group.read 0;" ::: "memory");
            }
        } else {
            asm volatile("bar.arrive 2, %0;" :: "n"(THREADS) : "memory");
            // warps 1-3 retire; warp 0 keeps the CTA (and SMEM) alive
        }
    } else {
        // partial tail tile (not hit when N % 8 == 0): direct stores
        #pragma unroll
        for (int i = 0; i < 2; i++) {
            const int n = r0 + i * HALF_ROWS + warp;
            if (n >= N) break;
            RowOut r = process_row(logits, regr, prop, n, lane, wmax, hmax);
            float4* bo = reinterpret_cast<float4*>(boxes_out) + (size_t)n * 81;
            bo[lane]      = r.box;
            bo[lane + 32] = r.box;
            if (lane < 17) bo[lane + 64] = r.box;
            float* so = scores_out + (size_t)n * 81;
            so[lane]      = r.sc0;
            so[lane + 32] = r.sc1;
            if (lane < 17) so[lane + 64] = r.sc2;
        }
    }
}

extern "C" void kernel_launch(void* const* d_in, const int* in_sizes, int n_in,
                              void* d_out, int out_size) {
    const float* logits = (const float*)d_in[0];
    const float* regr   = (const float*)d_in[1];
    const float* prop   = (const float*)d_in[2];
    const void*  imw    = d_in[3];
    const void*  imh    = d_in[4];

    const int N = in_sizes[0] / 81;          // 262144

    float* boxes  = (float*)d_out;           // N*81*4 floats
    float* scores = boxes + (size_t)N * 81 * 4;

    const int blocks = (N + ROWS_PER_BLOCK - 1) / ROWS_PER_BLOCK;  // 32768
    postproc_kernel<<<blocks, THREADS>>>(logits, regr, prop, imw, imh,
                                         boxes, scores, N);
}

// round 12
// speedup vs baseline: 1.0055x; 1.0055x over previous
#include <cuda_runtime.h>
#include <cuda_bf16.h>
#include <math_constants.h>

// BBOX_XFORM_CLIP = log(1000/16)
#define BBOX_XFORM_CLIP 4.135166556742356f

#define HALF_ROWS 4                  // rows per half-tile (one row per warp)
#define ROWS_PER_BLOCK (2 * HALF_ROWS)
#define THREADS 128                  // 4 warps

#define BOX_HALF_BYTES (HALF_ROWS * 81 * 16)   // 5184
#define SC_HALF_BYTES  (HALF_ROWS * 81 * 4)    // 1296

// img dims may arrive as int32 or float32; disambiguate by plausibility.
__device__ __forceinline__ float load_dim(const void* p) {
    int iv = *(const int*)p;
    if (iv > 0 && iv < (1 << 20)) return (float)iv;
    return __int_as_float(iv);
}

struct RowOut {
    float4 box;
    float sc0, sc1, sc2;
};

__device__ __forceinline__ RowOut process_row(
    const float* __restrict__ logits,
    const float* __restrict__ regr,
    const float* __restrict__ prop,
    int n, int lane, float wmax, float hmax)
{
    // front-batch all 5 independent loads (MLP=5) before any consumer
    const float4 b  = reinterpret_cast<const float4*>(prop)[n];
    const float4 rc = reinterpret_cast<const float4*>(regr)[n];

    const float* lrow = logits + (size_t)n * 81;
    float v0 = lrow[lane];
    float v1 = lrow[lane + 32];
    float v2 = (lane < 17) ? lrow[lane + 64] : -CUDART_INF_F;

    // ---------------- softmax over 81 logits ----------------
    float m = fmaxf(fmaxf(v0, v1), v2);
    #pragma unroll
    for (int o = 16; o; o >>= 1)
        m = fmaxf(m, __shfl_xor_sync(0xffffffffu, m, o));

    float e0 = __expf(v0 - m);
    float e1 = __expf(v1 - m);
    float e2 = (lane < 17) ? __expf(v2 - m) : 0.0f;

    float s = e0 + e1 + e2;
    #pragma unroll
    for (int o = 16; o; o >>= 1)
        s += __shfl_xor_sync(0xffffffffu, s, o);
    const float inv = __fdividef(1.0f, s);

    // ---------------- bbox decode (all lanes redundantly) ----------------
    const float w  = b.z - b.x + 1.0f;
    const float h  = b.w - b.y + 1.0f;
    const float cx = b.x + 0.5f * w;
    const float cy = b.y + 0.5f * h;

    const float dx = rc.x * 0.1f;
    const float dy = rc.y * 0.1f;
    const float dw = fminf(rc.z * 0.2f, BBOX_XFORM_CLIP);
    const float dh = fminf(rc.w * 0.2f, BBOX_XFORM_CLIP);

    const float pcx = dx * w + cx;
    const float pcy = dy * h + cy;
    const float pw  = __expf(dw) * w;
    const float ph  = __expf(dh) * h;

    float x1 = pcx - 0.5f * pw;
    float y1 = pcy - 0.5f * ph;
    float x2 = pcx + 0.5f * pw - 1.0f;
    float y2 = pcy + 0.5f * ph - 1.0f;

    // max(...,0) then clip(0,max) == clamp to [0,max]
    RowOut r;
    r.box = make_float4(fminf(fmaxf(x1, 0.0f), wmax),
                        fminf(fmaxf(y1, 0.0f), hmax),
                        fminf(fmaxf(x2, 0.0f), wmax),
                        fminf(fmaxf(y2, 0.0f), hmax));
    r.sc0 = e0 * inv;
    r.sc1 = e1 * inv;
    r.sc2 = e2 * inv;
    return r;
}

__device__ __forceinline__ void stage_row(float* s_box, float* s_sc,
                                          int lr, int lane, const RowOut& r)
{
    float4* sb = reinterpret_cast<float4*>(s_box) + lr * 81;
    sb[lane]      = r.box;
    sb[lane + 32] = r.box;
    if (lane < 17) sb[lane + 64] = r.box;

    float* ss = s_sc + lr * 81;
    ss[lane]      = r.sc0;
    ss[lane + 32] = r.sc1;
    if (lane < 17) ss[lane + 64] = r.sc2;
}

__device__ __forceinline__ void commit_half(const float* s_box, const float* s_sc,
                                            float* boxes_out, float* scores_out,
                                            long long half_idx)
{
    asm volatile("fence.proxy.async.shared::cta;" ::: "memory");
    unsigned sb_a = (unsigned)__cvta_generic_to_shared(s_box);
    unsigned ss_a = (unsigned)__cvta_generic_to_shared(s_sc);
    char* gb = (char*)boxes_out  + (size_t)half_idx * BOX_HALF_BYTES;
    char* gs = (char*)scores_out + (size_t)half_idx * SC_HALF_BYTES;
    asm volatile("cp.async.bulk.global.shared::cta.bulk_group [%0], [%1], %2;"
                 :: "l"(gb), "r"(sb_a), "n"(BOX_HALF_BYTES) : "memory");
    asm volatile("cp.async.bulk.global.shared::cta.bulk_group [%0], [%1], %2;"
                 :: "l"(gs), "r"(ss_a), "n"(SC_HALF_BYTES) : "memory");
    asm volatile("cp.async.bulk.commit_group;" ::: "memory");
}

__global__ void __launch_bounds__(THREADS)
postproc_kernel(const float* __restrict__ logits,       // [N,81]
                const float* __restrict__ regr,         // [N,4]
                const float* __restrict__ prop,         // [N,4]
                const void*  __restrict__ imw_p,
                const void*  __restrict__ imh_p,
                float* __restrict__ boxes_out,          // [N*81,4]
                float* __restrict__ scores_out,         // [N*81]
                int N)
{
    __shared__ alignas(16) float s_box[2][HALF_ROWS * 81 * 4];  // 2x5184 B
    __shared__ alignas(16) float s_sc [2][HALF_ROWS * 81];      // 2x1296 B

    const int warp = threadIdx.x >> 5;
    const int lane = threadIdx.x & 31;
    const int r0   = blockIdx.x * ROWS_PER_BLOCK;

    const float wmax = load_dim(imw_p) - 1.0f;
    const float hmax = load_dim(imh_p) - 1.0f;

    if (r0 + ROWS_PER_BLOCK <= N) {
        // ---------------- half A: all warps compute + stage ----------------
        {
            const int n = r0 + warp;
            RowOut r = process_row(logits, regr, prop, n, lane, wmax, hmax);
            stage_row(s_box[0], s_sc[0], warp, lane, r);
        }
        // barrier 1: warp 0 is the consumer (commits half A); others arrive
        if (warp == 0) {
            asm volatile("bar.sync 1, %0;" :: "n"(THREADS) : "memory");
            if (lane == 0)
                commit_half(s_box[0], s_sc[0], boxes_out, scores_out,
                            2LL * blockIdx.x);      // warp0's own bulk group
        } else {
            asm volatile("bar.arrive 1, %0;" :: "n"(THREADS) : "memory");
        }

        // ---------------- half B: overlaps half A's commit + drain ----------
        {
            const int n = r0 + HALF_ROWS + warp;
            RowOut r = process_row(logits, regr, prop, n, lane, wmax, hmax);
            stage_row(s_box[1], s_sc[1], warp, lane, r);
        }
        // barrier 2: warp 1 is the consumer (commits half B); others arrive.
        // bulk_group state is per-thread: warp0-lane0 waits on group A,
        // warp1-lane0 waits on group B. Both keep the CTA alive until their
        // group's SMEM reads complete.
        if (warp == 1) {
            asm volatile("bar.sync 2, %0;" :: "n"(THREADS) : "memory");
            if (lane == 0) {
                commit_half(s_box[1], s_sc[1], boxes_out, scores_out,
                            2LL * blockIdx.x + 1);
                asm volatile("cp.async.bulk.wait_group.read 0;" ::: "memory");
            }
        } else {
            asm volatile("bar.arrive 2, %0;" :: "n"(THREADS) : "memory");
            if (warp == 0 && lane == 0) {
                // wait for group A only (almost certainly already drained,
                // having overlapped all of half B's compute)
                asm volatile("cp.async.bulk.wait_group.read 0;" ::: "memory");
            }
        }
    } else {
        // partial tail tile (not hit when N % 8 == 0): direct stores
        #pragma unroll
        for (int i = 0; i < 2; i++) {
            const int n = r0 + i * HALF_ROWS + warp;
            if (n >= N) break;
            RowOut r = process_row(logits, regr, prop, n, lane, wmax, hmax);
            float4* bo = reinterpret_cast<float4*>(boxes_out) + (size_t)n * 81;
            bo[lane]      = r.box;
            bo[lane + 32] = r.box;
            if (lane < 17) bo[lane + 64] = r.box;
            float* so = scores_out + (size_t)n * 81;
            so[lane]      = r.sc0;
            so[lane + 32] = r.sc1;
            if (lane < 17) so[lane + 64] = r.sc2;
        }
    }
}

extern "C" void kernel_launch(void* const* d_in, const int* in_sizes, int n_in,
                              void* d_out, int out_size) {
    const float* logits = (const float*)d_in[0];
    const float* regr   = (const float*)d_in[1];
    const float* prop   = (const float*)d_in[2];
    const void*  imw    = d_in[3];
    const void*  imh    = d_in[4];

    const int N = in_sizes[0] / 81;          // 262144

    float* boxes  = (float*)d_out;           // N*81*4 floats
    float* scores = boxes + (size_t)N * 81 * 4;

    const int blocks = (N + ROWS_PER_BLOCK - 1) / ROWS_PER_BLOCK;  // 32768
    postproc_kernel<<<blocks, THREADS>>>(logits, regr, prop, imw, imh,
                                         boxes, scores, N);
}